// round 3
// baseline (speedup 1.0000x reference)
#include <cuda_runtime.h>
#include <math.h>

// Problem dims
#define TT 512
#define BB 256
#define FF 512
#define HH 512

// Tiling: grid = NM x NH = 4 x 32 = 128 CTAs, each owns a 64-batch x 16-hcol tile
// (=> 64 gate rows: the i/f/g/o quadruple for its 16 h columns).
#define MT 64
#define HT 16
#define NCTA 128
#define NTH 256
#define KC 16
#define NKC 64   // (FF+HH)/KC

// Packed dual-fp32 FMA: d.lo += a.lo*b.lo ; d.hi += a.hi*b.hi  (rt_SMSP=2 => 2x MACs vs FFMA)
#define FFMA2(d, a, b) asm("fma.rn.f32x2 %0, %1, %2, %0;" : "+l"(d) : "l"(a), "l"(b))

// Persistent device state (allocation-free scratch)
__device__ float g_h[2][BB * HH];      // ping-pong hidden state
__device__ unsigned g_count;           // barrier arrival counter
__device__ unsigned g_gen;             // barrier generation

__device__ __forceinline__ void grid_sync(unsigned target) {
    __syncthreads();
    if (threadIdx.x == 0) {
        __threadfence();
        if (atomicAdd(&g_count, 1u) == NCTA - 1) {
            atomicExch(&g_count, 0u);
            __threadfence();
            atomicExch(&g_gen, target);
        } else {
            volatile unsigned* p = &g_gen;
            while (*p != target) { }
        }
        __threadfence();
    }
    __syncthreads();
}

__device__ __forceinline__ float sigf(float v) { return 1.0f / (1.0f + expf(-v)); }

__global__ void __launch_bounds__(NTH, 1) lstm_persistent(
    const float* __restrict__ x,     // (T,B,F)
    const float* __restrict__ wih,   // (4H,F)
    const float* __restrict__ whh,   // (4H,H)
    const float* __restrict__ bih,   // (4H)
    const float* __restrict__ bhh,   // (4H)
    float* __restrict__ out)         // [B*T*H h_seq][B*H h_t][B*H c_t]
{
    // K-major staging. A values are DUPLICATED (a,a pairs) so one LDS.128 yields
    // two packed f32x2 operands with no pack-MOVs.
    __shared__ __align__(16) float As2[2][KC][2 * MT];  // 16 KB
    __shared__ __align__(16) float Bs[2][KC][MT];       // 8 KB (64 gate rows)
    __shared__ float Cs[MT][4 * HT + 1];                // 16.6 KB gate outputs

    const int tid = threadIdx.x;
    const int mi = blockIdx.x & 3;        // batch tile
    const int hi = blockIdx.x >> 2;       // h-col tile
    const int m0 = mi * MT;
    const int j0 = hi * HT;

    const unsigned base_gen = *(volatile unsigned*)&g_gen;

    // ---- init: zero h0 tile (this CTA's ownership region) ----
    for (int p = tid; p < MT * HT; p += NTH) {
        int r = p >> 4, jc = p & 15;
        g_h[0][(m0 + r) * HH + j0 + jc] = 0.0f;
    }

    // Loader indexing: thread loads one float4 per matrix per chunk.
    const int lrow = tid >> 2;            // 0..63 (A: batch row / B: gate row)
    const int lq   = (tid & 3) * 4;       // k sub-offset 0/4/8/12
    // B gather row: gate quadruple for this CTA's 16 h columns
    const int wrowB = (lrow >> 4) * HH + j0 + (lrow & 15);

    // Compute indexing: 16x16 threads, 4x4 micro-tile each
    const int ty = (tid >> 4) * 4;        // C-tile row base (batch)
    const int tx = (tid & 15) * 4;        // C-tile col base (gate row)

    // Elementwise: thread handles (r = tid>>4 + 16q, jj = tid&15), q=0..3
    const int jj = tid & 15;
    const float bias_i = bih[0 * HH + j0 + jj] + bhh[0 * HH + j0 + jj];
    const float bias_f = bih[1 * HH + j0 + jj] + bhh[1 * HH + j0 + jj];
    const float bias_g = bih[2 * HH + j0 + jj] + bhh[2 * HH + j0 + jj];
    const float bias_o = bih[3 * HH + j0 + jj] + bhh[3 * HH + j0 + jj];

    float c_reg[4] = {0.0f, 0.0f, 0.0f, 0.0f};   // cell state, register-resident

    grid_sync(base_gen + 1);

    for (int t = 0; t < TT; ++t) {
        const float* __restrict__ hrd = g_h[t & 1];
        float* __restrict__ hwr = g_h[(t + 1) & 1];
        const float* __restrict__ xt = x + (long)t * (BB * FF);

        // acc[i][p]: packed pair over gate-cols {tx+2p, tx+2p+1}, rows ty+i
        unsigned long long acc[4][2];
        #pragma unroll
        for (int i = 0; i < 4; ++i) { acc[i][0] = 0ull; acc[i][1] = 0ull; }

        // ---- prologue: chunk 0 (x / wih region) ----
        float4 av = *(const float4*)(xt + (m0 + lrow) * FF + lq);
        float4 bv = *(const float4*)(wih + wrowB * FF + lq);
        {
            #pragma unroll
            for (int i = 0; i < 4; ++i) {
                float v = (i == 0) ? av.x : (i == 1) ? av.y : (i == 2) ? av.z : av.w;
                *(float2*)&As2[0][lq + i][2 * lrow] = make_float2(v, v);
            }
            Bs[0][lq + 0][lrow] = bv.x; Bs[0][lq + 1][lrow] = bv.y;
            Bs[0][lq + 2][lrow] = bv.z; Bs[0][lq + 3][lrow] = bv.w;
        }
        __syncthreads();

        #pragma unroll 2
        for (int kc = 0; kc < NKC; ++kc) {
            const int cur = kc & 1;
            const bool more = (kc + 1 < NKC);
            if (more) {
                const int k0 = (kc + 1) * KC;
                if (k0 < FF) {
                    av = *(const float4*)(xt + (m0 + lrow) * FF + k0 + lq);
                    bv = *(const float4*)(wih + wrowB * FF + k0 + lq);
                } else {
                    // h from L2 (written by other CTAs last step; barrier-ordered)
                    av = __ldcg((const float4*)(hrd + (m0 + lrow) * HH + (k0 - FF) + lq));
                    bv = *(const float4*)(whh + wrowB * HH + (k0 - FF) + lq);
                }
            }
            #pragma unroll
            for (int k = 0; k < KC; ++k) {
                // (a0,a0,a1,a1) and (a2,a2,a3,a3) as packed 64-bit operands
                const ulonglong2 aA = *(const ulonglong2*)&As2[cur][k][2 * ty];
                const ulonglong2 aB = *(const ulonglong2*)&As2[cur][k][2 * ty + 4];
                const ulonglong2 bp = *(const ulonglong2*)&Bs[cur][k][tx];
                FFMA2(acc[0][0], aA.x, bp.x); FFMA2(acc[0][1], aA.x, bp.y);
                FFMA2(acc[1][0], aA.y, bp.x); FFMA2(acc[1][1], aA.y, bp.y);
                FFMA2(acc[2][0], aB.x, bp.x); FFMA2(acc[2][1], aB.x, bp.y);
                FFMA2(acc[3][0], aB.y, bp.x); FFMA2(acc[3][1], aB.y, bp.y);
            }
            if (more) {
                const int nb = cur ^ 1;
                #pragma unroll
                for (int i = 0; i < 4; ++i) {
                    float v = (i == 0) ? av.x : (i == 1) ? av.y : (i == 2) ? av.z : av.w;
                    *(float2*)&As2[nb][lq + i][2 * lrow] = make_float2(v, v);
                }
                Bs[nb][lq + 0][lrow] = bv.x; Bs[nb][lq + 1][lrow] = bv.y;
                Bs[nb][lq + 2][lrow] = bv.z; Bs[nb][lq + 3][lrow] = bv.w;
            }
            __syncthreads();
        }

        // ---- stage gates to smem so the elementwise thread sees its i/f/g/o ----
        #pragma unroll
        for (int i = 0; i < 4; ++i) {
            #pragma unroll
            for (int p = 0; p < 2; ++p) {
                float lo = __uint_as_float((unsigned)(acc[i][p] & 0xFFFFFFFFull));
                float hhi = __uint_as_float((unsigned)(acc[i][p] >> 32));
                Cs[ty + i][tx + 2 * p]     = lo;
                Cs[ty + i][tx + 2 * p + 1] = hhi;
            }
        }
        __syncthreads();

        // ---- elementwise gates + state update ----
        #pragma unroll
        for (int q = 0; q < 4; ++q) {
            const int r = (tid >> 4) + q * 16;          // batch-local row
            const float iv = Cs[r][0 * HT + jj] + bias_i;
            const float fv = Cs[r][1 * HT + jj] + bias_f;
            const float gv = Cs[r][2 * HT + jj] + bias_g;
            const float ov = Cs[r][3 * HT + jj] + bias_o;
            const float ig = sigf(iv);
            const float fg = sigf(fv);
            const float gg = tanhf(gv);
            const float og = sigf(ov);
            const float c  = fg * c_reg[q] + ig * gg;
            c_reg[q] = c;
            const float h  = og * tanhf(c);
            const int b = m0 + r;
            hwr[b * HH + j0 + jj] = h;
            out[(long)b * (TT * HH) + (long)t * HH + j0 + jj] = h;
            if (t == TT - 1) {
                out[(long)BB * TT * HH + b * HH + j0 + jj] = h;
                out[(long)BB * TT * HH + (long)BB * HH + b * HH + j0 + jj] = c;
            }
        }

        grid_sync(base_gen + 2 + t);
    }
}

extern "C" void kernel_launch(void* const* d_in, const int* in_sizes, int n_in,
                              void* d_out, int out_size) {
    const float* x   = (const float*)d_in[0];
    const float* wih = (const float*)d_in[1];
    const float* whh = (const float*)d_in[2];
    const float* bih = (const float*)d_in[3];
    const float* bhh = (const float*)d_in[4];
    float* out = (float*)d_out;
    (void)in_sizes; (void)n_in; (void)out_size;
    lstm_persistent<<<NCTA, NTH>>>(x, wih, whh, bih, bhh, out);
}

// round 4
// speedup vs baseline: 1.0019x; 1.0019x over previous
#include <cuda_runtime.h>
#include <math.h>

// Problem dims
#define TT 512
#define BB 256
#define FF 512
#define HH 512

// Tiling: grid = NM x NH = 4 x 32 = 128 CTAs, each owns a 64-batch x 16-hcol tile
// (=> 64 gate rows: the i/f/g/o quadruple for its 16 h columns).
#define MT 64
#define HT 16
#define NCTA 128
#define NTH 256
#define KC 16
#define NKC 64   // (FF+HH)/KC

// Packed dual-fp32 FMA: d.lo += a.lo*b.lo ; d.hi += a.hi*b.hi  (rt_SMSP=2 => 2x MACs vs FFMA)
#define FFMA2(d, a, b) asm("fma.rn.f32x2 %0, %1, %2, %0;" : "+l"(d) : "l"(a), "l"(b))

// Persistent device state (allocation-free scratch)
__device__ float g_h[2][BB * HH];      // ping-pong hidden state
__device__ unsigned g_count;           // barrier arrival counter
__device__ unsigned g_gen;             // barrier generation

__device__ __forceinline__ void grid_sync(unsigned target) {
    __syncthreads();
    if (threadIdx.x == 0) {
        __threadfence();
        if (atomicAdd(&g_count, 1u) == NCTA - 1) {
            atomicExch(&g_count, 0u);
            __threadfence();
            atomicExch(&g_gen, target);
        } else {
            volatile unsigned* p = &g_gen;
            while (*p != target) { }
        }
        __threadfence();
    }
    __syncthreads();
}

__device__ __forceinline__ float sigf(float v) { return 1.0f / (1.0f + expf(-v)); }

__global__ void __launch_bounds__(NTH, 1) lstm_persistent(
    const float* __restrict__ x,     // (T,B,F)
    const float* __restrict__ wih,   // (4H,F)
    const float* __restrict__ whh,   // (4H,H)
    const float* __restrict__ bih,   // (4H)
    const float* __restrict__ bhh,   // (4H)
    float* __restrict__ out)         // [B*T*H h_seq][B*H h_t][B*H c_t]
{
    // K-major staging. A values are DUPLICATED (a,a pairs) so one LDS.128 yields
    // two packed f32x2 operands with no pack-MOVs.
    __shared__ __align__(16) float As2[2][KC][2 * MT];  // 16 KB
    __shared__ __align__(16) float Bs[2][KC][MT];       // 8 KB (64 gate rows)
    __shared__ float Cs[MT][4 * HT + 1];                // 16.6 KB gate outputs

    const int tid = threadIdx.x;
    const int mi = blockIdx.x & 3;        // batch tile
    const int hi = blockIdx.x >> 2;       // h-col tile
    const int m0 = mi * MT;
    const int j0 = hi * HT;

    const unsigned base_gen = *(volatile unsigned*)&g_gen;

    // ---- init: zero h0 tile (this CTA's ownership region) ----
    for (int p = tid; p < MT * HT; p += NTH) {
        int r = p >> 4, jc = p & 15;
        g_h[0][(m0 + r) * HH + j0 + jc] = 0.0f;
    }

    // Loader indexing: thread loads one float4 per matrix per chunk.
    const int lrow = tid >> 2;            // 0..63 (A: batch row / B: gate row)
    const int lq   = (tid & 3) * 4;       // k sub-offset 0/4/8/12
    // B gather row: gate quadruple for this CTA's 16 h columns
    const int wrowB = (lrow >> 4) * HH + j0 + (lrow & 15);

    // Compute indexing: 16x16 threads, 4x4 micro-tile each
    const int ty = (tid >> 4) * 4;        // C-tile row base (batch)
    const int tx = (tid & 15) * 4;        // C-tile col base (gate row)

    // Elementwise: thread handles (r = tid>>4 + 16q, jj = tid&15), q=0..3
    const int jj = tid & 15;
    const float bias_i = bih[0 * HH + j0 + jj] + bhh[0 * HH + j0 + jj];
    const float bias_f = bih[1 * HH + j0 + jj] + bhh[1 * HH + j0 + jj];
    const float bias_g = bih[2 * HH + j0 + jj] + bhh[2 * HH + j0 + jj];
    const float bias_o = bih[3 * HH + j0 + jj] + bhh[3 * HH + j0 + jj];

    float c_reg[4] = {0.0f, 0.0f, 0.0f, 0.0f};   // cell state, register-resident

    grid_sync(base_gen + 1);

    for (int t = 0; t < TT; ++t) {
        const float* __restrict__ hrd = g_h[t & 1];
        float* __restrict__ hwr = g_h[(t + 1) & 1];
        const float* __restrict__ xt = x + (long)t * (BB * FF);

        // acc[i][p]: packed pair over gate-cols {tx+2p, tx+2p+1}, rows ty+i
        unsigned long long acc[4][2];
        #pragma unroll
        for (int i = 0; i < 4; ++i) { acc[i][0] = 0ull; acc[i][1] = 0ull; }

        // ---- prologue: chunk 0 (x / wih region) ----
        float4 av = *(const float4*)(xt + (m0 + lrow) * FF + lq);
        float4 bv = *(const float4*)(wih + wrowB * FF + lq);
        {
            #pragma unroll
            for (int i = 0; i < 4; ++i) {
                float v = (i == 0) ? av.x : (i == 1) ? av.y : (i == 2) ? av.z : av.w;
                *(float2*)&As2[0][lq + i][2 * lrow] = make_float2(v, v);
            }
            Bs[0][lq + 0][lrow] = bv.x; Bs[0][lq + 1][lrow] = bv.y;
            Bs[0][lq + 2][lrow] = bv.z; Bs[0][lq + 3][lrow] = bv.w;
        }
        __syncthreads();

        #pragma unroll 2
        for (int kc = 0; kc < NKC; ++kc) {
            const int cur = kc & 1;
            const bool more = (kc + 1 < NKC);
            if (more) {
                const int k0 = (kc + 1) * KC;
                if (k0 < FF) {
                    av = *(const float4*)(xt + (m0 + lrow) * FF + k0 + lq);
                    bv = *(const float4*)(wih + wrowB * FF + k0 + lq);
                } else {
                    // h from L2 (written by other CTAs last step; barrier-ordered)
                    av = __ldcg((const float4*)(hrd + (m0 + lrow) * HH + (k0 - FF) + lq));
                    bv = *(const float4*)(whh + wrowB * HH + (k0 - FF) + lq);
                }
            }
            #pragma unroll
            for (int k = 0; k < KC; ++k) {
                // (a0,a0,a1,a1) and (a2,a2,a3,a3) as packed 64-bit operands
                const ulonglong2 aA = *(const ulonglong2*)&As2[cur][k][2 * ty];
                const ulonglong2 aB = *(const ulonglong2*)&As2[cur][k][2 * ty + 4];
                const ulonglong2 bp = *(const ulonglong2*)&Bs[cur][k][tx];
                FFMA2(acc[0][0], aA.x, bp.x); FFMA2(acc[0][1], aA.x, bp.y);
                FFMA2(acc[1][0], aA.y, bp.x); FFMA2(acc[1][1], aA.y, bp.y);
                FFMA2(acc[2][0], aB.x, bp.x); FFMA2(acc[2][1], aB.x, bp.y);
                FFMA2(acc[3][0], aB.y, bp.x); FFMA2(acc[3][1], aB.y, bp.y);
            }
            if (more) {
                const int nb = cur ^ 1;
                #pragma unroll
                for (int i = 0; i < 4; ++i) {
                    float v = (i == 0) ? av.x : (i == 1) ? av.y : (i == 2) ? av.z : av.w;
                    *(float2*)&As2[nb][lq + i][2 * lrow] = make_float2(v, v);
                }
                Bs[nb][lq + 0][lrow] = bv.x; Bs[nb][lq + 1][lrow] = bv.y;
                Bs[nb][lq + 2][lrow] = bv.z; Bs[nb][lq + 3][lrow] = bv.w;
            }
            __syncthreads();
        }

        // ---- stage gates to smem so the elementwise thread sees its i/f/g/o ----
        #pragma unroll
        for (int i = 0; i < 4; ++i) {
            #pragma unroll
            for (int p = 0; p < 2; ++p) {
                float lo = __uint_as_float((unsigned)(acc[i][p] & 0xFFFFFFFFull));
                float hhi = __uint_as_float((unsigned)(acc[i][p] >> 32));
                Cs[ty + i][tx + 2 * p]     = lo;
                Cs[ty + i][tx + 2 * p + 1] = hhi;
            }
        }
        __syncthreads();

        // ---- elementwise gates + state update ----
        #pragma unroll
        for (int q = 0; q < 4; ++q) {
            const int r = (tid >> 4) + q * 16;          // batch-local row
            const float iv = Cs[r][0 * HT + jj] + bias_i;
            const float fv = Cs[r][1 * HT + jj] + bias_f;
            const float gv = Cs[r][2 * HT + jj] + bias_g;
            const float ov = Cs[r][3 * HT + jj] + bias_o;
            const float ig = sigf(iv);
            const float fg = sigf(fv);
            const float gg = tanhf(gv);
            const float og = sigf(ov);
            const float c  = fg * c_reg[q] + ig * gg;
            c_reg[q] = c;
            const float h  = og * tanhf(c);
            const int b = m0 + r;
            hwr[b * HH + j0 + jj] = h;
            out[(long)b * (TT * HH) + (long)t * HH + j0 + jj] = h;
            if (t == TT - 1) {
                out[(long)BB * TT * HH + b * HH + j0 + jj] = h;
                out[(long)BB * TT * HH + (long)BB * HH + b * HH + j0 + jj] = c;
            }
        }

        grid_sync(base_gen + 2 + t);
    }
}

extern "C" void kernel_launch(void* const* d_in, const int* in_sizes, int n_in,
                              void* d_out, int out_size) {
    const float* x   = (const float*)d_in[0];
    const float* wih = (const float*)d_in[1];
    const float* whh = (const float*)d_in[2];
    const float* bih = (const float*)d_in[3];
    const float* bhh = (const float*)d_in[4];
    float* out = (float*)d_out;
    (void)in_sizes; (void)n_in; (void)out_size;
    lstm_persistent<<<NCTA, NTH>>>(x, wih, whh, bih, bhh, out);
}

// round 6
// speedup vs baseline: 3.1440x; 3.1382x over previous
#include <cuda_runtime.h>
#include <cuda_bf16.h>
#include <stdint.h>
#include <math.h>

#define TT 512
#define BB 256
#define FF 512
#define HH 512
#define NCTA 128
#define NTH 256
#define ZP 144   // B-staging smem row pitch (bytes): 16B-aligned, conflict-free frags

// W in mma-fragment order: [mt 32][wm 4][kstep 64][split 2][lane 32] x uint4
__device__ uint4 g_Wf[32 * 4 * 64 * 2 * 32];
__device__ __nv_bfloat16 g_hhi[2][BB * HH];
__device__ __nv_bfloat16 g_hlo[2][BB * HH];
__device__ unsigned g_count, g_gen;

__device__ __forceinline__ unsigned pack2(float a, float b) {
    __nv_bfloat162 t; t.x = __float2bfloat16_rn(a); t.y = __float2bfloat16_rn(b);
    return *(unsigned*)&t;
}
__device__ __forceinline__ float sigf(float v) { return 1.0f / (1.0f + expf(-v)); }

#define MMA(c, a, b0, b1) \
    asm volatile("mma.sync.aligned.m16n8k16.row.col.f32.bf16.bf16.f32 " \
        "{%0,%1,%2,%3}, {%4,%5,%6,%7}, {%8,%9}, {%0,%1,%2,%3};" \
        : "+f"((c)[0]), "+f"((c)[1]), "+f"((c)[2]), "+f"((c)[3]) \
        : "r"((a).x), "r"((a).y), "r"((a).z), "r"((a).w), "r"(b0), "r"(b1))

// phase 0: gather W rows (i/f/g/o quadruples per 16-hcol group), split to bf16
// hi/lo, store in per-thread mma fragment order; zero h0 splits.
__global__ void phase0(const float* __restrict__ wih, const float* __restrict__ whh) {
    long id = (long)blockIdx.x * blockDim.x + threadIdx.x;
    long stride = (long)gridDim.x * blockDim.x;
    for (long i = id; i < 32L * 4 * 64 * 2 * 32; i += stride) {
        int lane = (int)(i & 31);
        long r1 = i >> 5;
        int split = (int)(r1 & 1);
        long r2 = r1 >> 1;
        int kstep = (int)(r2 & 63);
        long r3 = r2 >> 6;
        int wm = (int)(r3 & 3);
        int mt = (int)(r3 >> 2);
        int g = lane >> 2, c4 = lane & 3;
        int ka = kstep * 16 + 2 * c4;
        float e[2][4];
        #pragma unroll
        for (int rr = 0; rr < 2; ++rr) {
            int r = wm * 16 + g + rr * 8;                     // row in 64-row tile
            int orig = (r >> 4) * 512 + mt * 16 + (r & 15);   // original gate row
            #pragma unroll
            for (int kk = 0; kk < 4; ++kk) {
                int k = ka + (kk & 1) + (kk >> 1) * 8;
                float v = (k < 512) ? wih[(long)orig * 512 + k]
                                    : whh[(long)orig * 512 + k - 512];
                float hv = __bfloat162float(__float2bfloat16_rn(v));
                e[rr][kk] = split ? (v - hv) : v;
            }
        }
        uint4 o;
        o.x = pack2(e[0][0], e[0][1]);
        o.y = pack2(e[1][0], e[1][1]);
        o.z = pack2(e[0][2], e[0][3]);
        o.w = pack2(e[1][2], e[1][3]);
        g_Wf[i] = o;
    }
    __nv_bfloat16 z = __float2bfloat16_rn(0.0f);
    for (long i = id; i < (long)BB * HH; i += stride) { g_hhi[0][i] = z; g_hlo[0][i] = z; }
}

__global__ void __launch_bounds__(NTH, 1) lstm_mma(
    const float* __restrict__ x,
    const float* __restrict__ bih,
    const float* __restrict__ bhh,
    float* __restrict__ out)
{
    // B staging: [buf][split] 64 rows x 64 k bf16 at pitch ZP; Gs aliases zs[0]
    __shared__ __align__(16) char zs[2][2][64 * ZP];
    float* Gs = (float*)&zs[0][0][0];                 // 64 x 68 floats (17.4KB < 18.4KB)

    const int tid = threadIdx.x;
    const int wid = tid >> 5;
    const int lane = tid & 31;
    const int g = lane >> 2, c4 = lane & 3;
    const int wm = wid >> 1, wn = wid & 1;
    const int mt = blockIdx.x >> 2;                   // 0..31 gate-M tile
    const int nt = blockIdx.x & 3;                    // 0..3 batch tile
    const int b0 = nt * 64;
    const int nb = wn * 32;

    const unsigned base_gen = *(volatile unsigned*)&g_gen;
    const uint4* __restrict__ wf = g_Wf + (long)(mt * 4 + wm) * 64 * 2 * 32;

    // epilogue mapping
    const int jl = tid & 15;                          // h-col within tile
    const int brow = tid >> 4;                        // 0..15
    const int jg = mt * 16 + jl;                      // global h-col
    const float bias_i = bih[0 * 512 + jg] + bhh[0 * 512 + jg];
    const float bias_f = bih[1 * 512 + jg] + bhh[1 * 512 + jg];
    const float bias_g = bih[2 * 512 + jg] + bhh[2 * 512 + jg];
    const float bias_o = bih[3 * 512 + jg] + bhh[3 * 512 + jg];
    float c_reg[4] = {0.f, 0.f, 0.f, 0.f};

    for (int t = 0; t < TT; ++t) {
        const int par = t & 1, nxt = par ^ 1;
        float acc[4][4];
        #pragma unroll
        for (int i = 0; i < 4; ++i)
            #pragma unroll
            for (int j = 0; j < 4; ++j) acc[i][j] = 0.f;

        // ---- stage chunk 0 (x) ----
        {
            const float* xs = x + ((long)t * BB + b0) * FF;
            #pragma unroll
            for (int it = 0; it < 4; ++it) {
                int u = tid + it * 256;
                int row = u >> 4, k0 = (u & 15) * 4;
                float4 v = *(const float4*)(xs + (long)row * FF + k0);
                float hx = __bfloat162float(__float2bfloat16_rn(v.x));
                float hy = __bfloat162float(__float2bfloat16_rn(v.y));
                float hz = __bfloat162float(__float2bfloat16_rn(v.z));
                float hw = __bfloat162float(__float2bfloat16_rn(v.w));
                uint2 hi = make_uint2(pack2(hx, hy), pack2(hz, hw));
                uint2 lo = make_uint2(pack2(v.x - hx, v.y - hy), pack2(v.z - hz, v.w - hw));
                *(uint2*)(zs[0][0] + row * ZP + k0 * 2) = hi;
                *(uint2*)(zs[0][1] + row * ZP + k0 * 2) = lo;
            }
        }
        __syncthreads();

        for (int kc = 0; kc < 16; ++kc) {
            const int buf = kc & 1;
            const int nk = kc + 1;
            const bool pfx = (nk < 8);
            const bool pfh = (nk >= 8 && nk < 16 && !(nk == 8 && t > 0));
            float4 p0, p1, p2, p3;

            if (pfx) {
                const float* xs = x + ((long)t * BB + b0) * FF + nk * 64;
                int u0 = tid, r0 = u0 >> 4, k0 = (u0 & 15) * 4;
                int u1 = tid + 256, r1 = u1 >> 4, k1 = (u1 & 15) * 4;
                int u2 = tid + 512, r2 = u2 >> 4, k2 = (u2 & 15) * 4;
                int u3 = tid + 768, r3 = u3 >> 4, k3 = (u3 & 15) * 4;
                p0 = *(const float4*)(xs + (long)r0 * FF + k0);
                p1 = *(const float4*)(xs + (long)r1 * FF + k1);
                p2 = *(const float4*)(xs + (long)r2 * FF + k2);
                p3 = *(const float4*)(xs + (long)r3 * FF + k3);
            } else if (pfh) {
                const int hk = nk * 64 - 512;
                int u0 = tid, r0 = u0 >> 3, k0 = (u0 & 7) * 8;
                int u1 = tid + 256, r1 = u1 >> 3, k1 = (u1 & 7) * 8;
                p0 = __ldcg((const float4*)(g_hhi[par] + (b0 + r0) * HH + hk + k0));
                p1 = __ldcg((const float4*)(g_hhi[par] + (b0 + r1) * HH + hk + k1));
                p2 = __ldcg((const float4*)(g_hlo[par] + (b0 + r0) * HH + hk + k0));
                p3 = __ldcg((const float4*)(g_hlo[par] + (b0 + r1) * HH + hk + k1));
            }

            // ---- compute chunk kc ----
            {
                const uint4* wfb = wf + (long)(kc * 4) * 2 * 32;
                const char* zb0 = zs[buf][0];
                const char* zb1 = zs[buf][1];
                #pragma unroll
                for (int ks = 0; ks < 4; ++ks) {
                    uint4 Ah = __ldg(&wfb[(ks * 2 + 0) * 32 + lane]);
                    uint4 Al = __ldg(&wfb[(ks * 2 + 1) * 32 + lane]);
                    const char* zh = zb0 + ks * 32 + c4 * 4;
                    const char* zl = zb1 + ks * 32 + c4 * 4;
                    #pragma unroll
                    for (int n2 = 0; n2 < 4; ++n2) {
                        const int noff = (nb + n2 * 8 + g) * ZP;
                        unsigned bh0 = *(const unsigned*)(zh + noff);
                        unsigned bh1 = *(const unsigned*)(zh + noff + 16);
                        unsigned bl0 = *(const unsigned*)(zl + noff);
                        unsigned bl1 = *(const unsigned*)(zl + noff + 16);
                        MMA(acc[n2], Ah, bh0, bh1);
                        MMA(acc[n2], Ah, bl0, bl1);
                        MMA(acc[n2], Al, bh0, bh1);
                    }
                }
            }

            // ---- store prefetched chunk nk (or late barrier + stage for chunk 8) ----
            if (pfx) {
                char* d0 = zs[nk & 1][0];
                char* d1 = zs[nk & 1][1];
                #pragma unroll
                for (int it = 0; it < 4; ++it) {
                    int u = tid + it * 256;
                    int row = u >> 4, k0 = (u & 15) * 4;
                    float4 v = (it == 0) ? p0 : (it == 1) ? p1 : (it == 2) ? p2 : p3;
                    float hx = __bfloat162float(__float2bfloat16_rn(v.x));
                    float hy = __bfloat162float(__float2bfloat16_rn(v.y));
                    float hz = __bfloat162float(__float2bfloat16_rn(v.z));
                    float hw = __bfloat162float(__float2bfloat16_rn(v.w));
                    *(uint2*)(d0 + row * ZP + k0 * 2) = make_uint2(pack2(hx, hy), pack2(hz, hw));
                    *(uint2*)(d1 + row * ZP + k0 * 2) =
                        make_uint2(pack2(v.x - hx, v.y - hy), pack2(v.z - hz, v.w - hw));
                }
            } else if (pfh) {
                char* d0 = zs[nk & 1][0];
                char* d1 = zs[nk & 1][1];
                int u0 = tid, r0 = u0 >> 3, k0 = (u0 & 7) * 8;
                int u1 = tid + 256, r1 = u1 >> 3, k1 = (u1 & 7) * 8;
                *(float4*)(d0 + r0 * ZP + k0 * 2) = p0;
                *(float4*)(d0 + r1 * ZP + k1 * 2) = p1;
                *(float4*)(d1 + r0 * ZP + k0 * 2) = p2;
                *(float4*)(d1 + r1 * ZP + k1 * 2) = p3;
            } else if (kc == 7 && t > 0) {
                // wait for all CTAs to publish h_{t-1}, then stage chunk 8
                if (tid == 0) {
                    volatile unsigned* p = &g_gen;
                    while (*p - base_gen < (unsigned)t) { }
                }
                __syncthreads();
                const int hk = 0;
                char* d0 = zs[0][0];
                char* d1 = zs[0][1];
                #pragma unroll
                for (int it = 0; it < 2; ++it) {
                    int u = tid + it * 256;
                    int row = u >> 3, k0 = (u & 7) * 8;
                    *(float4*)(d0 + row * ZP + k0 * 2) =
                        __ldcg((const float4*)(g_hhi[par] + (b0 + row) * HH + hk + k0));
                    *(float4*)(d1 + row * ZP + k0 * 2) =
                        __ldcg((const float4*)(g_hlo[par] + (b0 + row) * HH + hk + k0));
                }
            }
            __syncthreads();
        }

        // ---- exchange gates via Gs (aliases zs[0]; last compute used zs[1]) ----
        #pragma unroll
        for (int n2 = 0; n2 < 4; ++n2) {
            const int col = nb + n2 * 8 + 2 * c4;
            const int row = wm * 16 + g;
            Gs[row * 68 + col] = acc[n2][0];
            Gs[row * 68 + col + 1] = acc[n2][1];
            Gs[(row + 8) * 68 + col] = acc[n2][2];
            Gs[(row + 8) * 68 + col + 1] = acc[n2][3];
        }
        __syncthreads();

        // ---- elementwise gates + state update ----
        #pragma unroll
        for (int q = 0; q < 4; ++q) {
            const int b = brow + 16 * q;
            const float iv = Gs[(0 + jl) * 68 + b] + bias_i;
            const float fv = Gs[(16 + jl) * 68 + b] + bias_f;
            const float gv = Gs[(32 + jl) * 68 + b] + bias_g;
            const float ov = Gs[(48 + jl) * 68 + b] + bias_o;
            const float c = sigf(fv) * c_reg[q] + sigf(iv) * tanhf(gv);
            c_reg[q] = c;
            const float h = sigf(ov) * tanhf(c);
            const long gi = (long)(b0 + b) * HH + jg;
            float hh = __bfloat162float(__float2bfloat16_rn(h));
            g_hhi[nxt][gi] = __float2bfloat16_rn(h);
            g_hlo[nxt][gi] = __float2bfloat16_rn(h - hh);
            out[(long)(b0 + b) * (TT * HH) + (long)t * HH + jg] = h;
            if (t == TT - 1) {
                out[(long)BB * TT * HH + gi] = h;
                out[(long)BB * TT * HH + (long)BB * HH + gi] = c;
            }
        }

        // ---- publish h + arrive ----
        __threadfence();
        __syncthreads();
        if (tid == 0) {
            if (atomicAdd(&g_count, 1u) == NCTA - 1) {
                atomicExch(&g_count, 0u);
                __threadfence();
                atomicExch(&g_gen, base_gen + (unsigned)t + 1u);
            }
        }
    }
}

extern "C" void kernel_launch(void* const* d_in, const int* in_sizes, int n_in,
                              void* d_out, int out_size) {
    const float* x   = (const float*)d_in[0];
    const float* wih = (const float*)d_in[1];
    const float* whh = (const float*)d_in[2];
    const float* bih = (const float*)d_in[3];
    const float* bhh = (const float*)d_in[4];
    float* out = (float*)d_out;
    (void)in_sizes; (void)n_in; (void)out_size;
    phase0<<<1024, 256>>>(wih, whh);
    lstm_mma<<<NCTA, NTH>>>(x, bih, bhh, out);
}

// round 7
// speedup vs baseline: 4.5005x; 1.4314x over previous
#include <cuda_runtime.h>
#include <cuda_bf16.h>
#include <stdint.h>
#include <math.h>

#define TT 512
#define BB 256
#define FF 512
#define HH 512
#define NCTA 128
#define NTH 256
#define ZP 144

// W in mma-fragment order: [mt 32][wm 4][kstep 64][split 2][lane 32] x uint4
__device__ uint4 g_Wf[32 * 4 * 64 * 2 * 32];
// gx = x*Wih^T + biases, in per-thread fragment order:
// [t][cid 128][wid 8] -> 512 floats (n2*128 + lane*4 + j)
__device__ float g_gx[512L * 128 * 8 * 512];
__device__ __nv_bfloat16 g_hhi[2][BB * HH];
__device__ __nv_bfloat16 g_hlo[2][BB * HH];
__device__ unsigned g_flag[4][32];   // [nt][mt]: steps completed

__device__ __forceinline__ unsigned pack2(float a, float b) {
    __nv_bfloat162 t; t.x = __float2bfloat16_rn(a); t.y = __float2bfloat16_rn(b);
    return *(unsigned*)&t;
}
__device__ __forceinline__ float sig_fast(float v) {
    return __fdividef(1.0f, 1.0f + __expf(-v));
}
__device__ __forceinline__ float tanh_fast(float v) {
    float e = __expf(-2.0f * fabsf(v));            // in (0,1]: no overflow
    return copysignf(__fdividef(1.0f - e, 1.0f + e), v);
}

#define MMA(c, a, b0, b1) \
    asm volatile("mma.sync.aligned.m16n8k16.row.col.f32.bf16.bf16.f32 " \
        "{%0,%1,%2,%3}, {%4,%5,%6,%7}, {%8,%9}, {%0,%1,%2,%3};" \
        : "+f"((c)[0]), "+f"((c)[1]), "+f"((c)[2]), "+f"((c)[3]) \
        : "r"((a).x), "r"((a).y), "r"((a).z), "r"((a).w), "r"(b0), "r"(b1))

// ---- phase 0: W gather/split to fragment order; zero h0; reset flags ----
__global__ void phase0(const float* __restrict__ wih, const float* __restrict__ whh) {
    long id = (long)blockIdx.x * blockDim.x + threadIdx.x;
    long stride = (long)gridDim.x * blockDim.x;
    for (long i = id; i < 32L * 4 * 64 * 2 * 32; i += stride) {
        int lane = (int)(i & 31);
        long r1 = i >> 5;
        int split = (int)(r1 & 1);
        long r2 = r1 >> 1;
        int kstep = (int)(r2 & 63);
        long r3 = r2 >> 6;
        int wm = (int)(r3 & 3);
        int mt = (int)(r3 >> 2);
        int g = lane >> 2, c4 = lane & 3;
        int ka = kstep * 16 + 2 * c4;
        float e[2][4];
        #pragma unroll
        for (int rr = 0; rr < 2; ++rr) {
            int r = wm * 16 + g + rr * 8;
            int orig = (r >> 4) * 512 + mt * 16 + (r & 15);
            #pragma unroll
            for (int kk = 0; kk < 4; ++kk) {
                int k = ka + (kk & 1) + (kk >> 1) * 8;
                float v = (k < 512) ? wih[(long)orig * 512 + k]
                                    : whh[(long)orig * 512 + k - 512];
                float hv = __bfloat162float(__float2bfloat16_rn(v));
                e[rr][kk] = split ? (v - hv) : v;
            }
        }
        uint4 o;
        o.x = pack2(e[0][0], e[0][1]);
        o.y = pack2(e[1][0], e[1][1]);
        o.z = pack2(e[0][2], e[0][3]);
        o.w = pack2(e[1][2], e[1][3]);
        g_Wf[i] = o;
    }
    __nv_bfloat16 z = __float2bfloat16_rn(0.0f);
    for (long i = id; i < (long)BB * HH; i += stride) { g_hhi[0][i] = z; g_hlo[0][i] = z; }
    if (id < 128) ((unsigned*)g_flag)[id] = 0;
}

// ---- phase 1: gx[t] = x_t * Wih^T + (bias_ih + bias_hh), fragment order ----
__global__ void __launch_bounds__(NTH, 1) phase1(
    const float* __restrict__ x,
    const float* __restrict__ bih,
    const float* __restrict__ bhh)
{
    __shared__ __align__(16) char zs[2][2][64 * ZP];
    const int tid = threadIdx.x;
    const int wid = tid >> 5;
    const int lane = tid & 31;
    const int g = lane >> 2, c4 = lane & 3;
    const int wm = wid >> 1, wn = wid & 1;
    const int cid = blockIdx.x & 127;
    const int tg = blockIdx.x >> 7;          // 0..15, 32 steps each
    const int mt = cid >> 2, nt = cid & 3;
    const int b0 = nt * 64;
    const int nb = wn * 32;
    const uint4* __restrict__ wf = g_Wf + (long)(mt * 4 + wm) * 64 * 2 * 32;

    // folded biases for this lane's two fragment rows
    const int r0 = wm * 16 + g, r1 = r0 + 8;
    const int o0 = (r0 >> 4) * 512 + mt * 16 + (r0 & 15);
    const int o1 = (r1 >> 4) * 512 + mt * 16 + (r1 & 15);
    const float b_r0 = bih[o0] + bhh[o0];
    const float b_r1 = bih[o1] + bhh[o1];

    for (int i = 0; i < 32; ++i) {
        const int t = tg * 32 + i;
        float acc[4][4];
        #pragma unroll
        for (int n2 = 0; n2 < 4; ++n2) {
            acc[n2][0] = b_r0; acc[n2][1] = b_r0;
            acc[n2][2] = b_r1; acc[n2][3] = b_r1;
        }
        const float* xs0 = x + ((long)t * BB + b0) * FF;
        // stage chunk 0
        #pragma unroll
        for (int it = 0; it < 4; ++it) {
            int u = tid + it * 256;
            int row = u >> 4, k0 = (u & 15) * 4;
            float4 v = *(const float4*)(xs0 + (long)row * FF + k0);
            float hx = __bfloat162float(__float2bfloat16_rn(v.x));
            float hy = __bfloat162float(__float2bfloat16_rn(v.y));
            float hz = __bfloat162float(__float2bfloat16_rn(v.z));
            float hw = __bfloat162float(__float2bfloat16_rn(v.w));
            *(uint2*)(zs[0][0] + row * ZP + k0 * 2) = make_uint2(pack2(hx, hy), pack2(hz, hw));
            *(uint2*)(zs[0][1] + row * ZP + k0 * 2) =
                make_uint2(pack2(v.x - hx, v.y - hy), pack2(v.z - hz, v.w - hw));
        }
        __syncthreads();

        for (int kc = 0; kc < 8; ++kc) {
            const int buf = kc & 1;
            const int nk = kc + 1;
            float4 p0, p1, p2, p3;
            if (nk < 8) {
                const float* xs = xs0 + nk * 64;
                int u0 = tid, u1 = tid + 256, u2 = tid + 512, u3 = tid + 768;
                p0 = *(const float4*)(xs + (long)(u0 >> 4) * FF + (u0 & 15) * 4);
                p1 = *(const float4*)(xs + (long)(u1 >> 4) * FF + (u1 & 15) * 4);
                p2 = *(const float4*)(xs + (long)(u2 >> 4) * FF + (u2 & 15) * 4);
                p3 = *(const float4*)(xs + (long)(u3 >> 4) * FF + (u3 & 15) * 4);
            }
            {
                const uint4* wfb = wf + (long)(kc * 4) * 2 * 32;
                const char* zb0 = zs[buf][0];
                const char* zb1 = zs[buf][1];
                #pragma unroll
                for (int ks = 0; ks < 4; ++ks) {
                    uint4 Ah = __ldg(&wfb[(ks * 2 + 0) * 32 + lane]);
                    uint4 Al = __ldg(&wfb[(ks * 2 + 1) * 32 + lane]);
                    const char* zh = zb0 + ks * 32 + c4 * 4;
                    const char* zl = zb1 + ks * 32 + c4 * 4;
                    #pragma unroll
                    for (int n2 = 0; n2 < 4; ++n2) {
                        const int noff = (nb + n2 * 8 + g) * ZP;
                        unsigned bh0 = *(const unsigned*)(zh + noff);
                        unsigned bh1 = *(const unsigned*)(zh + noff + 16);
                        unsigned bl0 = *(const unsigned*)(zl + noff);
                        unsigned bl1 = *(const unsigned*)(zl + noff + 16);
                        MMA(acc[n2], Ah, bh0, bh1);
                        MMA(acc[n2], Ah, bl0, bl1);
                        MMA(acc[n2], Al, bh0, bh1);
                    }
                }
            }
            if (nk < 8) {
                char* d0 = zs[nk & 1][0];
                char* d1 = zs[nk & 1][1];
                #pragma unroll
                for (int it = 0; it < 4; ++it) {
                    int u = tid + it * 256;
                    int row = u >> 4, k0 = (u & 15) * 4;
                    float4 v = (it == 0) ? p0 : (it == 1) ? p1 : (it == 2) ? p2 : p3;
                    float hx = __bfloat162float(__float2bfloat16_rn(v.x));
                    float hy = __bfloat162float(__float2bfloat16_rn(v.y));
                    float hz = __bfloat162float(__float2bfloat16_rn(v.z));
                    float hw = __bfloat162float(__float2bfloat16_rn(v.w));
                    *(uint2*)(d0 + row * ZP + k0 * 2) = make_uint2(pack2(hx, hy), pack2(hz, hw));
                    *(uint2*)(d1 + row * ZP + k0 * 2) =
                        make_uint2(pack2(v.x - hx, v.y - hy), pack2(v.z - hz, v.w - hw));
                }
            }
            __syncthreads();
        }
        // store acc in fragment order
        float* gp = g_gx + (((long)t * 128 + cid) * 8 + wid) * 512;
        #pragma unroll
        for (int n2 = 0; n2 < 4; ++n2)
            *(float4*)(gp + n2 * 128 + lane * 4) =
                make_float4(acc[n2][0], acc[n2][1], acc[n2][2], acc[n2][3]);
    }
}

// ---- phase 2: recurrence, h-half GEMM only ----
__global__ void __launch_bounds__(NTH, 1) lstm_loop(float* __restrict__ out) {
    __shared__ __align__(16) char zs[2][2][64 * ZP];
    float* Gs = (float*)&zs[0][0][0];     // 64 x 68 floats

    const int tid = threadIdx.x;
    const int wid = tid >> 5;
    const int lane = tid & 31;
    const int g = lane >> 2, c4 = lane & 3;
    const int wm = wid >> 1, wn = wid & 1;
    const int mt = blockIdx.x >> 2;
    const int nt = blockIdx.x & 3;
    const int b0 = nt * 64;
    const int nb = wn * 32;
    const uint4* __restrict__ wf = g_Wf + (long)(mt * 4 + wm) * 64 * 2 * 32;

    const int jl = tid & 15;
    const int brow = tid >> 4;
    const int jg = mt * 16 + jl;
    float c_reg[4] = {0.f, 0.f, 0.f, 0.f};

    for (int t = 0; t < TT; ++t) {
        const int par = t & 1, nxt = par ^ 1;

        // acc init from gx (independent of h: issue before the flag wait)
        float acc[4][4];
        {
            const float* gp = g_gx + (((long)t * 128 + blockIdx.x) * 8 + wid) * 512;
            #pragma unroll
            for (int n2 = 0; n2 < 4; ++n2) {
                float4 v = __ldcg((const float4*)(gp + n2 * 128 + lane * 4));
                acc[n2][0] = v.x; acc[n2][1] = v.y; acc[n2][2] = v.z; acc[n2][3] = v.w;
            }
        }

        // wait for all producers of my batch rows to finish step t-1
        if (t > 0 && tid < 32) {
            volatile unsigned* f = &g_flag[nt][tid];
            while (*f < (unsigned)t) { }
        }
        __syncthreads();

        // stage h chunk 0
        #pragma unroll
        for (int it = 0; it < 2; ++it) {
            int u = tid + it * 256;
            int r = u >> 3, k0 = (u & 7) * 8;
            *(float4*)(zs[0][0] + r * ZP + k0 * 2) =
                __ldcg((const float4*)(g_hhi[par] + (b0 + r) * HH + k0));
            *(float4*)(zs[0][1] + r * ZP + k0 * 2) =
                __ldcg((const float4*)(g_hlo[par] + (b0 + r) * HH + k0));
        }
        __syncthreads();

        for (int kc = 0; kc < 8; ++kc) {
            const int buf = kc & 1;
            const int nk = kc + 1;
            float4 p0, p1, p2, p3;
            if (nk < 8) {
                const int hk = nk * 64;
                int u0 = tid, r0 = u0 >> 3, k0 = (u0 & 7) * 8;
                int u1 = tid + 256, r1 = u1 >> 3, k1 = (u1 & 7) * 8;
                p0 = __ldcg((const float4*)(g_hhi[par] + (b0 + r0) * HH + hk + k0));
                p1 = __ldcg((const float4*)(g_hhi[par] + (b0 + r1) * HH + hk + k1));
                p2 = __ldcg((const float4*)(g_hlo[par] + (b0 + r0) * HH + hk + k0));
                p3 = __ldcg((const float4*)(g_hlo[par] + (b0 + r1) * HH + hk + k1));
            }
            {
                const uint4* wfb = wf + (long)((kc + 8) * 4) * 2 * 32;
                const char* zb0 = zs[buf][0];
                const char* zb1 = zs[buf][1];
                #pragma unroll
                for (int ks = 0; ks < 4; ++ks) {
                    uint4 Ah = __ldg(&wfb[(ks * 2 + 0) * 32 + lane]);
                    uint4 Al = __ldg(&wfb[(ks * 2 + 1) * 32 + lane]);
                    const char* zh = zb0 + ks * 32 + c4 * 4;
                    const char* zl = zb1 + ks * 32 + c4 * 4;
                    #pragma unroll
                    for (int n2 = 0; n2 < 4; ++n2) {
                        const int noff = (nb + n2 * 8 + g) * ZP;
                        unsigned bh0 = *(const unsigned*)(zh + noff);
                        unsigned bh1 = *(const unsigned*)(zh + noff + 16);
                        unsigned bl0 = *(const unsigned*)(zl + noff);
                        unsigned bl1 = *(const unsigned*)(zl + noff + 16);
                        MMA(acc[n2], Ah, bh0, bh1);
                        MMA(acc[n2], Ah, bl0, bl1);
                        MMA(acc[n2], Al, bh0, bh1);
                    }
                }
            }
            if (nk < 8) {
                char* d0 = zs[nk & 1][0];
                char* d1 = zs[nk & 1][1];
                int u0 = tid, r0 = u0 >> 3, k0 = (u0 & 7) * 8;
                int u1 = tid + 256, r1 = u1 >> 3, k1 = (u1 & 7) * 8;
                *(float4*)(d0 + r0 * ZP + k0 * 2) = p0;
                *(float4*)(d0 + r1 * ZP + k1 * 2) = p1;
                *(float4*)(d1 + r0 * ZP + k0 * 2) = p2;
                *(float4*)(d1 + r1 * ZP + k1 * 2) = p3;
            }
            __syncthreads();
        }

        // exchange gates via Gs (last compute used zs[1]; zs[0] reads done)
        #pragma unroll
        for (int n2 = 0; n2 < 4; ++n2) {
            const int col = nb + n2 * 8 + 2 * c4;
            const int row = wm * 16 + g;
            Gs[row * 68 + col] = acc[n2][0];
            Gs[row * 68 + col + 1] = acc[n2][1];
            Gs[(row + 8) * 68 + col] = acc[n2][2];
            Gs[(row + 8) * 68 + col + 1] = acc[n2][3];
        }
        __syncthreads();

        // elementwise gates + state update (biases already folded in gx)
        #pragma unroll
        for (int q = 0; q < 4; ++q) {
            const int b = brow + 16 * q;
            const float iv = Gs[(0 + jl) * 68 + b];
            const float fv = Gs[(16 + jl) * 68 + b];
            const float gv = Gs[(32 + jl) * 68 + b];
            const float ov = Gs[(48 + jl) * 68 + b];
            const float c = sig_fast(fv) * c_reg[q] + sig_fast(iv) * tanh_fast(gv);
            c_reg[q] = c;
            const float h = sig_fast(ov) * tanh_fast(c);
            const long gi = (long)(b0 + b) * HH + jg;
            float hh = __bfloat162float(__float2bfloat16_rn(h));
            g_hhi[nxt][gi] = __float2bfloat16_rn(h);
            g_hlo[nxt][gi] = __float2bfloat16_rn(h - hh);
            out[(long)(b0 + b) * (TT * HH) + (long)t * HH + jg] = h;
            if (t == TT - 1) {
                out[(long)BB * TT * HH + gi] = h;
                out[(long)BB * TT * HH + (long)BB * HH + gi] = c;
            }
        }

        __threadfence();
        __syncthreads();
        if (tid == 0) atomicExch(&g_flag[nt][mt], (unsigned)(t + 1));
    }
}

extern "C" void kernel_launch(void* const* d_in, const int* in_sizes, int n_in,
                              void* d_out, int out_size) {
    const float* x   = (const float*)d_in[0];
    const float* wih = (const float*)d_in[1];
    const float* whh = (const float*)d_in[2];
    const float* bih = (const float*)d_in[3];
    const float* bhh = (const float*)d_in[4];
    float* out = (float*)d_out;
    (void)in_sizes; (void)n_in; (void)out_size;
    phase0<<<1024, 256>>>(wih, whh);
    phase1<<<2048, NTH>>>(x, bih, bhh);
    lstm_loop<<<NCTA, NTH>>>(out);
}